// round 14
// baseline (speedup 1.0000x reference)
#include <cuda_runtime.h>
#include <cuda_bf16.h>
#include <cstdint>

// Problem constants
#define B_    32
#define CIN_  64
#define Hh    32
#define Ww    32
#define CO_   64
#define KK    7
#define G_    8
#define PAD_  3
#define HP    38            // padded side
#define NPIX  (HP*HP)       // 1444

// Scratch (no cudaMalloc allowed)
__device__ float g_q[B_ * Hh * Ww * CO_];        // [b][hw][o]
__device__ float g_k[B_ * NPIX * CO_];           // [b][pp][o]
__device__ float g_v[B_ * NPIX * CO_];           // [b][pp][o]

// ---- packed fp32 helpers ---------------------------------------------------
#define PACKF(out, lo, hi) \
    asm("mov.b64 %0, {%1, %2};" : "=l"(out) : "f"(lo), "f"(hi))
#define UNPACKF(lo, hi, in) \
    asm("mov.b64 {%0, %1}, %2;" : "=f"(lo), "=f"(hi) : "l"(in))
#define FFMA2(d, a, b) \
    asm("fma.rn.f32x2 %0, %1, %2, %0;" : "+l"(d) : "l"(a), "l"(b))

// ---- bf16 HMMA m16n8k16 ----------------------------------------------------
__device__ __forceinline__ void mma16816(float* d, const uint32_t* a,
                                         uint32_t b0, uint32_t b1) {
    asm volatile(
        "mma.sync.aligned.m16n8k16.row.col.f32.bf16.bf16.f32 "
        "{%0,%1,%2,%3}, {%4,%5,%6,%7}, {%8,%9}, {%0,%1,%2,%3};"
        : "+f"(d[0]), "+f"(d[1]), "+f"(d[2]), "+f"(d[3])
        : "r"(a[0]), "r"(a[1]), "r"(a[2]), "r"(a[3]), "r"(b0), "r"(b1));
}

__device__ __forceinline__ uint32_t pack_bf16_hi(float x0, float x1,
                                                 float& r0, float& r1) {
    __nv_bfloat16 h0 = __float2bfloat16(x0);
    __nv_bfloat16 h1 = __float2bfloat16(x1);
    r0 = x0 - __bfloat162float(h0);
    r1 = x1 - __bfloat162float(h1);
    return ((uint32_t)__bfloat16_as_ushort(h1) << 16) | __bfloat16_as_ushort(h0);
}
__device__ __forceinline__ uint32_t pack_bf16(float x0, float x1) {
    return ((uint32_t)__bfloat16_as_ushort(__float2bfloat16(x1)) << 16) |
           __bfloat16_as_ushort(__float2bfloat16(x0));
}

// ---------------------------------------------------------------------------
// HMMA projection + fused setup. CTA = 128 interior pixels of one batch,
// 256 threads. Also: per-CTA weight split (coalesced L2 reads) and a slice
// of the k/v border zeroing (disjoint records, no race with interior writes).
// ---------------------------------------------------------------------------
#define SA      36                        // A row stride in u32
#define A_PLANE (128 * SA)                // 4608 u32
#define BROW    32                        // B row stride in u32
#define B_PLANE (192 * BROW)              // 6144 u32
#define OFF_AH  0
#define OFF_AL  (A_PLANE)
#define OFF_BH  (2 * A_PLANE)
#define OFF_BL  (2 * A_PLANE + B_PLANE)
#define SMEM_TC ((2 * A_PLANE + 2 * B_PLANE) * 4)   // 86016 bytes
#define NBORDER 420                       // 1444 - 1024 border pixels

__global__ __launch_bounds__(256) void proj_tc_kernel(
    const float* __restrict__ x,
    const float* __restrict__ wq,
    const float* __restrict__ wk,
    const float* __restrict__ wv) {
    extern __shared__ uint32_t sm32[];
    const int tid = threadIdx.x;
    const int b   = blockIdx.x >> 3;
    const int bi  = blockIdx.x & 7;
    const int p0  = bi * 128;                        // interior pixel base

    // ---- border zeroing slice: CTA bi zeroes border px [bi*53, ...) -------
    {
        int j0 = bi * 53;
        int j1 = (bi == 7) ? NBORDER : j0 + 53;
        for (int t = j0 * 16 + tid; t < j1 * 16; t += 256) {
            int bj = t >> 4, c4 = t & 15;
            int pp;
            if (bj < 114)       pp = bj;                 // rows 0..2
            else if (bj < 228)  pp = 1330 + (bj - 114);  // rows 35..37
            else {
                int t2  = bj - 228;
                int row = t2 / 6;
                int cc  = t2 - row * 6;
                pp = (row + PAD_) * HP + (cc < 3 ? cc : cc + 32);
            }
            size_t slot = (((size_t)(b * NPIX + pp)) << 4) | c4;
            float4 z = make_float4(0.f, 0.f, 0.f, 0.f);
            ((float4*)g_k)[slot] = z;
            ((float4*)g_v)[slot] = z;
        }
    }

    // ---- A fill: x fp32 -> bf16 hi/lo pairs (pair along c), [px][c2] ------
    const float* xb = x + (size_t)b * 65536;
    for (int i = tid; i < 4096; i += 256) {
        int px = i & 127, c2 = i >> 7;
        float x0 = xb[(2 * c2) * 1024 + p0 + px];
        float x1 = xb[(2 * c2 + 1) * 1024 + p0 + px];
        float r0, r1;
        sm32[OFF_AH + px * SA + c2] = pack_bf16_hi(x0, x1, r0, r1);
        sm32[OFF_AL + px * SA + c2] = pack_bf16(r0, r1);
    }
    // ---- B fill: split weights inline (coalesced, L2-hot), rotated cols ---
    for (int i = tid; i < 6144; i += 256) {
        int n = i >> 5, c2 = i & 31;
        int m = n >> 6, oc = n & 63;
        const float* W = (m == 0) ? wq : (m == 1 ? wk : wv);
        float v0 = W[oc * 64 + 2 * c2];
        float v1 = W[oc * 64 + 2 * c2 + 1];
        float r0, r1;
        uint32_t hp = pack_bf16_hi(v0, v1, r0, r1);
        uint32_t lp = pack_bf16(r0, r1);
        int sc = (c2 + 4 * (n & 7)) & 31;
        sm32[OFF_BH + n * BROW + sc] = hp;
        sm32[OFF_BL + n * BROW + sc] = lp;
    }
    __syncthreads();

    const int w   = tid >> 5;
    const int t   = tid & 31;
    const int qid = t >> 2;
    const int q4  = t & 3;

    uint32_t ah[4][4], al[4][4];
    {
        int r0 = 16 * w + qid;
#pragma unroll
        for (int kt = 0; kt < 4; kt++) {
            int cidx = kt * 8 + q4;
            ah[kt][0] = sm32[OFF_AH + r0 * SA + cidx];
            ah[kt][1] = sm32[OFF_AH + (r0 + 8) * SA + cidx];
            ah[kt][2] = sm32[OFF_AH + r0 * SA + cidx + 4];
            ah[kt][3] = sm32[OFF_AH + (r0 + 8) * SA + cidx + 4];
            al[kt][0] = sm32[OFF_AL + r0 * SA + cidx];
            al[kt][1] = sm32[OFF_AL + (r0 + 8) * SA + cidx];
            al[kt][2] = sm32[OFF_AL + r0 * SA + cidx + 4];
            al[kt][3] = sm32[OFF_AL + (r0 + 8) * SA + cidx + 4];
        }
    }

    const int pixA = p0 + 16 * w + qid;
    const int pixB = pixA + 8;
    const int ppA  = ((pixA >> 5) + PAD_) * HP + (pixA & 31) + PAD_;
    const int ppB  = ((pixB >> 5) + PAD_) * HP + (pixB & 31) + PAD_;
    const int rot  = 4 * qid;

#pragma unroll
    for (int m = 0; m < 3; m++) {
        float d[8][4];
#pragma unroll
        for (int nt = 0; nt < 8; nt++)
#pragma unroll
            for (int j = 0; j < 4; j++) d[nt][j] = 0.f;

#pragma unroll
        for (int kt = 0; kt < 4; kt++) {
            int c0 = kt * 8 + q4;
            int s0 = (c0 + rot) & 31;
            int s1 = (c0 + 4 + rot) & 31;
#pragma unroll
            for (int nt = 0; nt < 8; nt++) {
                int nb = (m * 64 + nt * 8 + qid) * BROW;
                uint32_t bh0 = sm32[OFF_BH + nb + s0];
                uint32_t bh1 = sm32[OFF_BH + nb + s1];
                uint32_t bl0 = sm32[OFF_BL + nb + s0];
                uint32_t bl1 = sm32[OFF_BL + nb + s1];
                mma16816(d[nt], ah[kt], bh0, bh1);   // xh*wh
                mma16816(d[nt], ah[kt], bl0, bl1);   // xh*wl
                mma16816(d[nt], al[kt], bh0, bh1);   // xl*wh
            }
        }

        float* baseA;
        float* baseB;
        if (m == 0) {
            baseA = g_q + (size_t)(b * 1024 + pixA) * 64;
            baseB = g_q + (size_t)(b * 1024 + pixB) * 64;
        } else {
            float* dst = (m == 1) ? g_k : g_v;
            baseA = dst + (size_t)(b * NPIX + ppA) * 64;
            baseB = dst + (size_t)(b * NPIX + ppB) * 64;
        }
#pragma unroll
        for (int nt = 0; nt < 8; nt++) {
            int c = nt * 8 + q4 * 2;
            *(float2*)(baseA + c) = make_float2(d[nt][0], d[nt][1]);
            *(float2*)(baseB + c) = make_float2(d[nt][2], d[nt][3]);
        }
    }
}

// ---------------------------------------------------------------------------
// Attention: CTA = (b, g, 16-row tile). 512 threads, thread = one pixel,
// packed f32x2 for channel dots/accumulation (R12 math, fp32 k and v).
// ---------------------------------------------------------------------------
#define TROWS 16
#define TPIX  836   // (TROWS + KK - 1) * HP = 22*38

__global__ __launch_bounds__(512) void attn_kernel(const float* __restrict__ rel_h,
                                                   const float* __restrict__ rel_w,
                                                   const float* __restrict__ cur,
                                                   float* __restrict__ out) {
    const int h0 = blockIdx.x * TROWS;
    const int g  = blockIdx.y;
    const int b  = blockIdx.z;

    __shared__ __align__(16) float k_s[2 * TPIX * 4];   // two 4-ch planes
    __shared__ __align__(16) float v_s[2 * TPIX * 4];
    float4* ks4 = (float4*)k_s;
    float4* vs4 = (float4*)v_s;

    const float4* gk4 = (const float4*)g_k + (size_t)(b * NPIX + h0 * HP) * 16 + g * 2;
    const float4* gv4 = (const float4*)g_v + (size_t)(b * NPIX + h0 * HP) * 16 + g * 2;
    for (int idx = threadIdx.x; idx < 2 * TPIX; idx += 512) {
        int pp = idx >> 1, c4 = idx & 1;
        ks4[c4 * TPIX + pp] = gk4[pp * 16 + c4];
        vs4[c4 * TPIX + pp] = gv4[pp * 16 + c4];
    }
    __syncthreads();

    const int r = threadIdx.x >> 5;        // local row 0..15
    const int w = threadIdx.x & 31;        // column
    const int h = h0 + r;

    const float4* qp = (const float4*)(g_q + (size_t)(b * 1024 + h * 32 + w) * 64 + g * 8);
    float4 qa = qp[0], qb = qp[1];
    float q[8] = {qa.x, qa.y, qa.z, qa.w, qb.x, qb.y, qb.z, qb.w};
    unsigned long long qpk[4];
#pragma unroll
    for (int c = 0; c < 4; c++) PACKF(qpk[c], q[2 * c], q[2 * c + 1]);

    float rel[7];
    {
        const float* rb = (g < 4) ? (rel_h + g * 56) : (rel_w + (g - 4) * 56);
#pragma unroll
        for (int t = 0; t < 7; t++) {
            float s = 0.f;
#pragma unroll
            for (int c = 0; c < 8; c++) s += q[c] * rb[c * 7 + t];
            rel[t] = s;
        }
    }

    const ulonglong2* ks2 = (const ulonglong2*)k_s;
    const ulonglong2* vs2 = (const ulonglong2*)v_s;

    float sc[49];
#pragma unroll
    for (int i = 0; i < 7; i++) {
        int base = (r + i) * HP + w;
#pragma unroll
        for (int j = 0; j < 7; j++) {
            int pix = base + j;
            ulonglong2 ka = ks2[pix];
            ulonglong2 kb = ks2[TPIX + pix];
            unsigned long long t;
            PACKF(t, (g < 4) ? rel[i] : rel[j], 0.f);
            FFMA2(t, ka.x, qpk[0]); FFMA2(t, ka.y, qpk[1]);
            FFMA2(t, kb.x, qpk[2]); FFMA2(t, kb.y, qpk[3]);
            float lo, hi; UNPACKF(lo, hi, t);
            sc[i * 7 + j] = lo + hi;
        }
    }

    float m = sc[0];
#pragma unroll
    for (int s = 1; s < 49; s++) m = fmaxf(m, sc[s]);
    float sum = 0.f;
#pragma unroll
    for (int s = 0; s < 49; s++) { sc[s] = __expf(sc[s] - m); sum += sc[s]; }

    unsigned long long oa[4] = {0, 0, 0, 0};
#pragma unroll
    for (int i = 0; i < 7; i++) {
        int base = (r + i) * HP + w;
#pragma unroll
        for (int j = 0; j < 7; j++) {
            int pix = base + j;
            float p = sc[i * 7 + j];
            unsigned long long pp; PACKF(pp, p, p);
            ulonglong2 va = vs2[pix];
            ulonglong2 vb = vs2[TPIX + pix];
            FFMA2(oa[0], pp, va.x); FFMA2(oa[1], pp, va.y);
            FFMA2(oa[2], pp, vb.x); FFMA2(oa[3], pp, vb.y);
        }
    }

    float inv = 1.f / sum;
    int rr = min(h, 31 - h);
    int lo = (h <= 31 - h) ? rr : rr + 1;
    int hi = 31 - rr;
    float om = ((float)(rr - 15) + cur[g] * 16.f) / 3.f + 1.f;
    om = fminf(fmaxf(om, 0.f), 1.f);
    float mk = (w >= lo && w <= hi) ? om : 1.f;
    float scal = inv * mk;

    float o0, o1, o2, o3, o4, o5, o6, o7;
    UNPACKF(o0, o1, oa[0]); UNPACKF(o2, o3, oa[1]);
    UNPACKF(o4, o5, oa[2]); UNPACKF(o6, o7, oa[3]);
    float* op = out + (size_t)(b * 64 + g * 8) * 1024 + h * 32 + w;
    op[0]        = o0 * scal; op[1024]     = o1 * scal;
    op[2 * 1024] = o2 * scal; op[3 * 1024] = o3 * scal;
    op[4 * 1024] = o4 * scal; op[5 * 1024] = o5 * scal;
    op[6 * 1024] = o6 * scal; op[7 * 1024] = o7 * scal;
}

// ---------------------------------------------------------------------------
extern "C" void kernel_launch(void* const* d_in, const int* in_sizes, int n_in,
                              void* d_out, int out_size) {
    const float* x  = (const float*)d_in[0];
    const float* wq = (const float*)d_in[1];
    const float* wk = (const float*)d_in[2];
    const float* wv = (const float*)d_in[3];
    const float* rh = (const float*)d_in[4];
    const float* rw = (const float*)d_in[5];
    const float* cv = (const float*)d_in[6];
    float* out = (float*)d_out;

    cudaFuncSetAttribute(proj_tc_kernel,
                         cudaFuncAttributeMaxDynamicSharedMemorySize, SMEM_TC);

    proj_tc_kernel<<<256, 256, SMEM_TC>>>(x, wq, wk, wv);
    attn_kernel<<<dim3(Hh / TROWS, G_, B_), 512>>>(rh, rw, cv, out);
}

// round 15
// speedup vs baseline: 1.2048x; 1.2048x over previous
#include <cuda_runtime.h>
#include <cuda_bf16.h>
#include <cstdint>

// Problem constants
#define B_    32
#define CIN_  64
#define Hh    32
#define Ww    32
#define CO_   64
#define KK    7
#define G_    8
#define PAD_  3
#define HP    38            // padded side
#define NPIX  (HP*HP)       // 1444

// Scratch (no cudaMalloc allowed)
__device__ float g_q[B_ * Hh * Ww * CO_];        // [b][hw][o]
__device__ float g_k[B_ * NPIX * CO_];           // [b][pp][o]
__device__ float g_v[B_ * NPIX * CO_];           // [b][pp][o]

// ---- packed fp32 helpers ---------------------------------------------------
#define PACKF(out, lo, hi) \
    asm("mov.b64 %0, {%1, %2};" : "=l"(out) : "f"(lo), "f"(hi))
#define UNPACKF(lo, hi, in) \
    asm("mov.b64 {%0, %1}, %2;" : "=f"(lo), "=f"(hi) : "l"(in))
#define FFMA2(d, a, b) \
    asm("fma.rn.f32x2 %0, %1, %2, %0;" : "+l"(d) : "l"(a), "l"(b))

// ---- bf16 HMMA m16n8k16 ----------------------------------------------------
__device__ __forceinline__ void mma16816(float* d, const uint32_t* a,
                                         uint32_t b0, uint32_t b1) {
    asm volatile(
        "mma.sync.aligned.m16n8k16.row.col.f32.bf16.bf16.f32 "
        "{%0,%1,%2,%3}, {%4,%5,%6,%7}, {%8,%9}, {%0,%1,%2,%3};"
        : "+f"(d[0]), "+f"(d[1]), "+f"(d[2]), "+f"(d[3])
        : "r"(a[0]), "r"(a[1]), "r"(a[2]), "r"(a[3]), "r"(b0), "r"(b1));
}

__device__ __forceinline__ uint32_t pack_bf16_hi(float x0, float x1,
                                                 float& r0, float& r1) {
    __nv_bfloat16 h0 = __float2bfloat16(x0);
    __nv_bfloat16 h1 = __float2bfloat16(x1);
    r0 = x0 - __bfloat162float(h0);
    r1 = x1 - __bfloat162float(h1);
    return ((uint32_t)__bfloat16_as_ushort(h1) << 16) | __bfloat16_as_ushort(h0);
}
__device__ __forceinline__ uint32_t pack_bf16(float x0, float x1) {
    return ((uint32_t)__bfloat16_as_ushort(__float2bfloat16(x1)) << 16) |
           __bfloat16_as_ushort(__float2bfloat16(x0));
}

// ---------------------------------------------------------------------------
// HMMA projection + fused setup (R14, measured ~12us). CTA = 128 interior
// pixels, 256 threads; fuses weight split + k/v border zeroing.
// ---------------------------------------------------------------------------
#define SA      36                        // A row stride in u32
#define A_PLANE (128 * SA)
#define BROW    32                        // B row stride in u32
#define B_PLANE (192 * BROW)
#define OFF_AH  0
#define OFF_AL  (A_PLANE)
#define OFF_BH  (2 * A_PLANE)
#define OFF_BL  (2 * A_PLANE + B_PLANE)
#define SMEM_TC ((2 * A_PLANE + 2 * B_PLANE) * 4)   // 86016 bytes
#define NBORDER 420

__global__ __launch_bounds__(256) void proj_tc_kernel(
    const float* __restrict__ x,
    const float* __restrict__ wq,
    const float* __restrict__ wk,
    const float* __restrict__ wv) {
    extern __shared__ uint32_t sm32[];
    const int tid = threadIdx.x;
    const int b   = blockIdx.x >> 3;
    const int bi  = blockIdx.x & 7;
    const int p0  = bi * 128;

    // border zeroing slice
    {
        int j0 = bi * 53;
        int j1 = (bi == 7) ? NBORDER : j0 + 53;
        for (int t = j0 * 16 + tid; t < j1 * 16; t += 256) {
            int bj = t >> 4, c4 = t & 15;
            int pp;
            if (bj < 114)       pp = bj;
            else if (bj < 228)  pp = 1330 + (bj - 114);
            else {
                int t2  = bj - 228;
                int row = t2 / 6;
                int cc  = t2 - row * 6;
                pp = (row + PAD_) * HP + (cc < 3 ? cc : cc + 32);
            }
            size_t slot = (((size_t)(b * NPIX + pp)) << 4) | c4;
            float4 z = make_float4(0.f, 0.f, 0.f, 0.f);
            ((float4*)g_k)[slot] = z;
            ((float4*)g_v)[slot] = z;
        }
    }

    const float* xb = x + (size_t)b * 65536;
    for (int i = tid; i < 4096; i += 256) {
        int px = i & 127, c2 = i >> 7;
        float x0 = xb[(2 * c2) * 1024 + p0 + px];
        float x1 = xb[(2 * c2 + 1) * 1024 + p0 + px];
        float r0, r1;
        sm32[OFF_AH + px * SA + c2] = pack_bf16_hi(x0, x1, r0, r1);
        sm32[OFF_AL + px * SA + c2] = pack_bf16(r0, r1);
    }
    for (int i = tid; i < 6144; i += 256) {
        int n = i >> 5, c2 = i & 31;
        int m = n >> 6, oc = n & 63;
        const float* W = (m == 0) ? wq : (m == 1 ? wk : wv);
        float v0 = W[oc * 64 + 2 * c2];
        float v1 = W[oc * 64 + 2 * c2 + 1];
        float r0, r1;
        uint32_t hp = pack_bf16_hi(v0, v1, r0, r1);
        uint32_t lp = pack_bf16(r0, r1);
        int sc = (c2 + 4 * (n & 7)) & 31;
        sm32[OFF_BH + n * BROW + sc] = hp;
        sm32[OFF_BL + n * BROW + sc] = lp;
    }
    __syncthreads();

    const int w   = tid >> 5;
    const int t   = tid & 31;
    const int qid = t >> 2;
    const int q4  = t & 3;

    uint32_t ah[4][4], al[4][4];
    {
        int r0 = 16 * w + qid;
#pragma unroll
        for (int kt = 0; kt < 4; kt++) {
            int cidx = kt * 8 + q4;
            ah[kt][0] = sm32[OFF_AH + r0 * SA + cidx];
            ah[kt][1] = sm32[OFF_AH + (r0 + 8) * SA + cidx];
            ah[kt][2] = sm32[OFF_AH + r0 * SA + cidx + 4];
            ah[kt][3] = sm32[OFF_AH + (r0 + 8) * SA + cidx + 4];
            al[kt][0] = sm32[OFF_AL + r0 * SA + cidx];
            al[kt][1] = sm32[OFF_AL + (r0 + 8) * SA + cidx];
            al[kt][2] = sm32[OFF_AL + r0 * SA + cidx + 4];
            al[kt][3] = sm32[OFF_AL + (r0 + 8) * SA + cidx + 4];
        }
    }

    const int pixA = p0 + 16 * w + qid;
    const int pixB = pixA + 8;
    const int ppA  = ((pixA >> 5) + PAD_) * HP + (pixA & 31) + PAD_;
    const int ppB  = ((pixB >> 5) + PAD_) * HP + (pixB & 31) + PAD_;
    const int rot  = 4 * qid;

#pragma unroll
    for (int m = 0; m < 3; m++) {
        float d[8][4];
#pragma unroll
        for (int nt = 0; nt < 8; nt++)
#pragma unroll
            for (int j = 0; j < 4; j++) d[nt][j] = 0.f;

#pragma unroll
        for (int kt = 0; kt < 4; kt++) {
            int c0 = kt * 8 + q4;
            int s0 = (c0 + rot) & 31;
            int s1 = (c0 + 4 + rot) & 31;
#pragma unroll
            for (int nt = 0; nt < 8; nt++) {
                int nb = (m * 64 + nt * 8 + qid) * BROW;
                uint32_t bh0 = sm32[OFF_BH + nb + s0];
                uint32_t bh1 = sm32[OFF_BH + nb + s1];
                uint32_t bl0 = sm32[OFF_BL + nb + s0];
                uint32_t bl1 = sm32[OFF_BL + nb + s1];
                mma16816(d[nt], ah[kt], bh0, bh1);
                mma16816(d[nt], ah[kt], bl0, bl1);
                mma16816(d[nt], al[kt], bh0, bh1);
            }
        }

        float* baseA;
        float* baseB;
        if (m == 0) {
            baseA = g_q + (size_t)(b * 1024 + pixA) * 64;
            baseB = g_q + (size_t)(b * 1024 + pixB) * 64;
        } else {
            float* dst = (m == 1) ? g_k : g_v;
            baseA = dst + (size_t)(b * NPIX + ppA) * 64;
            baseB = dst + (size_t)(b * NPIX + ppB) * 64;
        }
#pragma unroll
        for (int nt = 0; nt < 8; nt++) {
            int c = nt * 8 + q4 * 2;
            *(float2*)(baseA + c) = make_float2(d[nt][0], d[nt][1]);
            *(float2*)(baseB + c) = make_float2(d[nt][2], d[nt][3]);
        }
    }
}

// ---------------------------------------------------------------------------
// Attention (R6 version, measured 36.2us): CTA = (b, g, 8-row tile).
// 128 threads, thread = 2 adjacent rows at one column (shares the 8x7 k/v
// window between the two rows).
// ---------------------------------------------------------------------------
#define TROWS 8
#define TPIX  532   // (TROWS + KK - 1) * HP = 14*38

__global__ __launch_bounds__(128) void attn_kernel(const float* __restrict__ rel_h,
                                                   const float* __restrict__ rel_w,
                                                   const float* __restrict__ cur,
                                                   float* __restrict__ out) {
    const int h0 = blockIdx.x * TROWS;
    const int g  = blockIdx.y;
    const int b  = blockIdx.z;

    __shared__ __align__(16) float k_s[2 * TPIX * 4];
    __shared__ __align__(16) float v_s[2 * TPIX * 4];
    float4* ks4 = (float4*)k_s;
    float4* vs4 = (float4*)v_s;

    const float4* gk4 = (const float4*)g_k + (size_t)(b * NPIX + h0 * HP) * 16 + g * 2;
    const float4* gv4 = (const float4*)g_v + (size_t)(b * NPIX + h0 * HP) * 16 + g * 2;
    for (int idx = threadIdx.x; idx < 2 * TPIX; idx += 128) {
        int pp = idx >> 1, c4 = idx & 1;
        ks4[c4 * TPIX + pp] = gk4[pp * 16 + c4];
        vs4[c4 * TPIX + pp] = gv4[pp * 16 + c4];
    }
    __syncthreads();

    const int rp = threadIdx.x >> 5;       // row-pair 0..3
    const int w  = threadIdx.x & 31;       // column
    const int hA = h0 + rp * 2;
    const int hB = hA + 1;

    const float4* qPA = (const float4*)(g_q + (size_t)(b * 1024 + hA * 32 + w) * 64 + g * 8);
    const float4* qPB = (const float4*)(g_q + (size_t)(b * 1024 + hB * 32 + w) * 64 + g * 8);
    float4 a0 = qPA[0], a1 = qPA[1];
    float4 b0 = qPB[0], b1 = qPB[1];
    float qA[8] = {a0.x, a0.y, a0.z, a0.w, a1.x, a1.y, a1.z, a1.w};
    float qB[8] = {b0.x, b0.y, b0.z, b0.w, b1.x, b1.y, b1.z, b1.w};
    unsigned long long qAp[4], qBp[4];
#pragma unroll
    for (int c = 0; c < 4; c++) {
        PACKF(qAp[c], qA[2 * c], qA[2 * c + 1]);
        PACKF(qBp[c], qB[2 * c], qB[2 * c + 1]);
    }

    float relA[7], relB[7];
    {
        const float* rb = (g < 4) ? (rel_h + g * 56) : (rel_w + (g - 4) * 56);
#pragma unroll
        for (int t = 0; t < 7; t++) {
            float sA = 0.f, sB = 0.f;
#pragma unroll
            for (int c = 0; c < 8; c++) {
                float rv = rb[c * 7 + t];
                sA += qA[c] * rv;
                sB += qB[c] * rv;
            }
            relA[t] = sA; relB[t] = sB;
        }
    }

    const ulonglong2* ks2 = (const ulonglong2*)k_s;
    const ulonglong2* vs2 = (const ulonglong2*)v_s;

    float scA[49], scB[49];
#pragma unroll
    for (int i = 0; i < 8; i++) {
        int rowbase = (rp * 2 + i) * HP + w;
#pragma unroll
        for (int j = 0; j < 7; j++) {
            int pix = rowbase + j;
            ulonglong2 ka = ks2[pix];
            ulonglong2 kb = ks2[TPIX + pix];
            if (i < 7) {
                unsigned long long t;
                PACKF(t, (g < 4) ? relA[i] : relA[j], 0.f);
                FFMA2(t, ka.x, qAp[0]); FFMA2(t, ka.y, qAp[1]);
                FFMA2(t, kb.x, qAp[2]); FFMA2(t, kb.y, qAp[3]);
                float lo, hi; UNPACKF(lo, hi, t);
                scA[i * 7 + j] = lo + hi;
            }
            if (i > 0) {
                unsigned long long t;
                PACKF(t, (g < 4) ? relB[i - 1] : relB[j], 0.f);
                FFMA2(t, ka.x, qBp[0]); FFMA2(t, ka.y, qBp[1]);
                FFMA2(t, kb.x, qBp[2]); FFMA2(t, kb.y, qBp[3]);
                float lo, hi; UNPACKF(lo, hi, t);
                scB[(i - 1) * 7 + j] = lo + hi;
            }
        }
    }

    float mA = scA[0], mB = scB[0];
#pragma unroll
    for (int s = 1; s < 49; s++) { mA = fmaxf(mA, scA[s]); mB = fmaxf(mB, scB[s]); }
    float sumA = 0.f, sumB = 0.f;
#pragma unroll
    for (int s = 0; s < 49; s++) {
        scA[s] = __expf(scA[s] - mA); sumA += scA[s];
        scB[s] = __expf(scB[s] - mB); sumB += scB[s];
    }

    unsigned long long oA[4] = {0, 0, 0, 0}, oB[4] = {0, 0, 0, 0};
#pragma unroll
    for (int i = 0; i < 8; i++) {
        int rowbase = (rp * 2 + i) * HP + w;
#pragma unroll
        for (int j = 0; j < 7; j++) {
            int pix = rowbase + j;
            ulonglong2 va = vs2[pix];
            ulonglong2 vb = vs2[TPIX + pix];
            if (i < 7) {
                float p = scA[i * 7 + j];
                unsigned long long pp; PACKF(pp, p, p);
                FFMA2(oA[0], pp, va.x); FFMA2(oA[1], pp, va.y);
                FFMA2(oA[2], pp, vb.x); FFMA2(oA[3], pp, vb.y);
            }
            if (i > 0) {
                float p = scB[(i - 1) * 7 + j];
                unsigned long long pp; PACKF(pp, p, p);
                FFMA2(oB[0], pp, va.x); FFMA2(oB[1], pp, va.y);
                FFMA2(oB[2], pp, vb.x); FFMA2(oB[3], pp, vb.y);
            }
        }
    }

    const float cg = cur[g];
    {
        float inv = 1.f / sumA;
        int rr = min(hA, 31 - hA);
        int lo = (hA <= 31 - hA) ? rr : rr + 1;
        int hi = 31 - rr;
        float om = ((float)(rr - 15) + cg * 16.f) / 3.f + 1.f;
        om = fminf(fmaxf(om, 0.f), 1.f);
        float mk = (w >= lo && w <= hi) ? om : 1.f;
        float scal = inv * mk;
        float o0, o1, o2, o3, o4, o5, o6, o7;
        UNPACKF(o0, o1, oA[0]); UNPACKF(o2, o3, oA[1]);
        UNPACKF(o4, o5, oA[2]); UNPACKF(o6, o7, oA[3]);
        float* op = out + (size_t)(b * 64 + g * 8) * 1024 + hA * 32 + w;
        op[0]        = o0 * scal; op[1024]     = o1 * scal;
        op[2 * 1024] = o2 * scal; op[3 * 1024] = o3 * scal;
        op[4 * 1024] = o4 * scal; op[5 * 1024] = o5 * scal;
        op[6 * 1024] = o6 * scal; op[7 * 1024] = o7 * scal;
    }
    {
        float inv = 1.f / sumB;
        int rr = min(hB, 31 - hB);
        int lo = (hB <= 31 - hB) ? rr : rr + 1;
        int hi = 31 - rr;
        float om = ((float)(rr - 15) + cg * 16.f) / 3.f + 1.f;
        om = fminf(fmaxf(om, 0.f), 1.f);
        float mk = (w >= lo && w <= hi) ? om : 1.f;
        float scal = inv * mk;
        float o0, o1, o2, o3, o4, o5, o6, o7;
        UNPACKF(o0, o1, oB[0]); UNPACKF(o2, o3, oB[1]);
        UNPACKF(o4, o5, oB[2]); UNPACKF(o6, o7, oB[3]);
        float* op = out + (size_t)(b * 64 + g * 8) * 1024 + hB * 32 + w;
        op[0]        = o0 * scal; op[1024]     = o1 * scal;
        op[2 * 1024] = o2 * scal; op[3 * 1024] = o3 * scal;
        op[4 * 1024] = o4 * scal; op[5 * 1024] = o5 * scal;
        op[6 * 1024] = o6 * scal; op[7 * 1024] = o7 * scal;
    }
}

// ---------------------------------------------------------------------------
extern "C" void kernel_launch(void* const* d_in, const int* in_sizes, int n_in,
                              void* d_out, int out_size) {
    const float* x  = (const float*)d_in[0];
    const float* wq = (const float*)d_in[1];
    const float* wk = (const float*)d_in[2];
    const float* wv = (const float*)d_in[3];
    const float* rh = (const float*)d_in[4];
    const float* rw = (const float*)d_in[5];
    const float* cv = (const float*)d_in[6];
    float* out = (float*)d_out;

    cudaFuncSetAttribute(proj_tc_kernel,
                         cudaFuncAttributeMaxDynamicSharedMemorySize, SMEM_TC);

    proj_tc_kernel<<<256, 256, SMEM_TC>>>(x, wq, wk, wv);
    attn_kernel<<<dim3(Hh / TROWS, G_, B_), 128>>>(rh, rw, cv, out);
}